// round 16
// baseline (speedup 1.0000x reference)
#include <cuda_runtime.h>
#include <cuda_fp16.h>
#include <math.h>

#define TT 8
#define HS 48
#define FN 2304          // 48*48
#define FL 1024          // C*S*S
#define HH 192
#define WW 192
#define NB 32            // n*t*G

// ---------------- scratch ----------------
__device__ float  g_iT [(size_t)TT*FN*FL];        // idx1 transposed (fp32: argmax path)
__device__ __half g_sT [(size_t)TT*FN*3*FL];      // s1/s2/s3 interleaved [t][src][tn][c]
__device__ float  g_CN [(size_t)FN*FL];
__device__ float  g_convQ[(size_t)4*128*FN];      // Q-half conv out (per g, shared over t)
__device__ float  g_convK[(size_t)NB*128*FN];     // K-half conv out (per b)
__device__ float  g_gp [(size_t)NB*FN*2];
__device__ float  g_csoft[FN];
__device__ int    g_gidx [TT*FN];
__device__ float  g_inorm[TT*FN];
__device__ float  g_sspart[(size_t)16*TT*FN];
__device__ __half g_fusedT[(size_t)HH*WW*192];    // pixel-major fused features
__device__ uint4  g_wpk[4*9*12*32];               // fusion weights as mma A-fragments
__device__ float4 g_lnpk[256];                    // packed {gamma, beta, w0, w1} per channel

// Abramowitz–Stegun 7.1.26 erf, |abs err| <= ~1.5e-7
__device__ __forceinline__ float erf_fast(float x){
    float ax = fabsf(x);
    float t = __fdividef(1.0f, fmaf(0.3275911f, ax, 1.0f));
    float p = fmaf(t, 1.061405429f, -1.453152027f);
    p = fmaf(t, p, 1.421413741f);
    p = fmaf(t, p, -0.284496736f);
    p = fmaf(t, p, 0.254829592f);
    p = p * t;
    float e = __expf(-ax*ax);
    float r = fmaf(-p, e, 1.0f);
    return copysignf(r, x);
}

__device__ __forceinline__ unsigned pkh(float a, float b){
    return (unsigned)__half_as_ushort(__float2half(a))
         | ((unsigned)__half_as_ushort(__float2half(b)) << 16);
}

// ---------------- K: MERGED [idx1 transpose + norm partials] + [cn unfold/normalize] ----------------
__global__ void __launch_bounds__(256) k_trIcn(const float* __restrict__ idx1,
                                               const float* __restrict__ curr){
    __shared__ float tile[64][65];
    int bid = blockIdx.x;
    int tid = threadIdx.x;

    if (bid < 4608){
        int t = bid / 576;
        int rem = bid - t*576;
        int f0 = (rem % 36)*64, c0 = (rem / 36)*64;
        const float* src = idx1 + (size_t)t*FL*FN;
        #pragma unroll
        for (int k = 0; k < 4; k++){
            int u = tid + k*256;
            int c = u >> 4, q = u & 15;
            float4 v = *(const float4*)(src + (size_t)(c0+c)*FN + f0 + q*4);
            tile[c][q*4+0] = v.x; tile[c][q*4+1] = v.y;
            tile[c][q*4+2] = v.z; tile[c][q*4+3] = v.w;
        }
        __syncthreads();
        #pragma unroll
        for (int k = 0; k < 4; k++){
            int u = tid + k*256;
            int f = u >> 4, q = u & 15;
            float4 v = make_float4(tile[q*4+0][f], tile[q*4+1][f],
                                   tile[q*4+2][f], tile[q*4+3][f]);
            *(float4*)(g_iT + ((size_t)t*FN + f0+f)*FL + c0 + q*4) = v;
            float s = v.x*v.x + v.y*v.y + v.z*v.z + v.w*v.w;
            s += __shfl_xor_sync(~0u, s, 1);
            s += __shfl_xor_sync(~0u, s, 2);
            s += __shfl_xor_sync(~0u, s, 4);
            s += __shfl_xor_sync(~0u, s, 8);
            if (q == 0)
                g_sspart[(size_t)(rem/36)*(TT*FN) + t*FN + f0+f] = s;
        }
        return;
    }

    // ---- cn block ----
    int f = bid - 4608;
    int fy = f / HS, fx = f - fy*HS;
    float v[4]; float ss = 0.f;
    #pragma unroll
    for (int k = 0; k < 4; k++){
        int cf = k*256 + tid;
        int c = cf >> 4, rem = cf & 15, sy = rem >> 2, sx = rem & 3;
        float x = curr[((size_t)c*HH + (fy*4+sy))*WW + (fx*4+sx)];
        v[k] = x; ss += x*x;
    }
    for (int o = 16; o > 0; o >>= 1) ss += __shfl_xor_sync(~0u, ss, o);
    float* ws = &tile[0][0];
    float* invs = &tile[0][8];
    if ((tid & 31) == 0) ws[tid>>5] = ss;
    __syncthreads();
    if (tid == 0){
        float s = 0.f;
        #pragma unroll
        for (int k = 0; k < 8; k++) s += ws[k];
        *invs = 1.0f / fmaxf(sqrtf(s), 1e-12f);
    }
    __syncthreads();
    float iv = *invs;
    #pragma unroll
    for (int k = 0; k < 4; k++) g_CN[(size_t)f*FL + k*256 + tid] = v[k]*iv;
}

// ---------------- K: gidx + inorm finalize + wpack + ln-param pack ----------------
// grid: 127 blocks. bid<72: prep; bid in [72,126): wpack; bid==126: lnpk.
__global__ void k_prep(const float* __restrict__ loc, const float* __restrict__ wfus,
                       const float* __restrict__ lng, const float* __restrict__ lnb,
                       const float* __restrict__ wtpw){
    int bid = blockIdx.x;
    int tid = threadIdx.x;
    if (bid < 72){
        int i = bid*256 + tid;
        int t = i / FN, f = i - t*FN;
        float lx = loc[(t*2+0)*FN + f];
        float ly = loc[(t*2+1)*FN + f];
        int ix = __float2int_rn(lx);
        int iy = __float2int_rn(ly);
        bool valid = (ix>=0 && ix<HS && iy>=0 && iy<HS);
        g_gidx[i] = valid ? (iy*HS + ix) : -1;
        float s = 0.f;
        #pragma unroll
        for (int k = 0; k < 16; k++) s += g_sspart[(size_t)k*(TT*FN) + i];
        g_inorm[i] = 1.0f / fmaxf(sqrtf(s), 1e-12f);
        return;
    }
    if (bid < 126){
        int idx = (bid - 72)*256 + tid;       // < 13824 = 4*9*12*32
        int lane = idx & 31;
        int rest = idx >> 5;
        int kc = rest % 12; rest /= 12;
        int tap = rest % 9;
        int ocq = rest / 9;
        int g = lane >> 2, tg = lane & 3;
        int r0 = ocq*16 + g, r1 = r0 + 8;
        int k0 = kc*16 + tg*2;
        #define WF(r,k) wfus[((size_t)(r)*192 + (k))*9 + tap]
        uint4 u;
        u.x = pkh(WF(r0, k0),   WF(r0, k0+1));
        u.y = pkh(WF(r1, k0),   WF(r1, k0+1));
        u.z = pkh(WF(r0, k0+8), WF(r0, k0+9));
        u.w = pkh(WF(r1, k0+8), WF(r1, k0+9));
        #undef WF
        g_wpk[idx] = u;
        return;
    }
    // bid == 126: pack ln params
    g_lnpk[tid] = make_float4(lng[tid], lnb[tid], wtpw[tid], wtpw[256 + tid]);
}

// ---------------- K: grouped 5x5 conv, 2 out-ch/block, spatial-split, Q deduped ----------------
__global__ void __launch_bounds__(192, 8) k_conv(const float* __restrict__ wtdw,
                                                 const float* __restrict__ btdw){
    __shared__ float p[4*1456];               // 4 planes x 28 rows x 52
    __shared__ float w[100];
    __shared__ float bsm[2];
    int op = blockIdx.x;
    int yb = blockIdx.y;
    int half = blockIdx.z;
    bool isQ = (yb < 4);
    int g, t = 0, bb = 0;
    if (isQ){ g = yb; } else { bb = yb - 4; t = bb >> 2; g = bb & 3; }
    int o0 = (isQ ? 0 : 128) + op*2;
    int ch0 = g*256 + op*4;
    int tid = threadIdx.x;
    for (int i = tid; i < 100; i += 192) w[i] = wtdw[(size_t)o0*50 + i];
    if (tid < 2) bsm[tid] = btdw[o0 + tid];
    int ybase = half*24 - 2;
    for (int pix = tid; pix < 1456; pix += 192){
        int yy = pix/52 + ybase, xx = pix%52 - 2;
        float4 v = make_float4(0.f,0.f,0.f,0.f);
        if (yy >= 0 && yy < HS && xx >= 0 && xx < HS){
            int f = yy*HS + xx;
            if (isQ){
                v = *(const float4*)(g_CN + (size_t)f*FL + ch0);
            } else {
                int idx = g_gidx[t*FN + f];
                if (idx >= 0){
                    float inr = g_inorm[t*FN + idx];
                    v = *(const float4*)(g_iT + ((size_t)t*FN + idx)*FL + ch0);
                    v.x *= inr; v.y *= inr; v.z *= inr; v.w *= inr;
                }
            }
        }
        p[0*1456 + pix] = v.x;
        p[1*1456 + pix] = v.y;
        p[2*1456 + pix] = v.z;
        p[3*1456 + pix] = v.w;
    }
    __syncthreads();
    int x  = tid % 48;
    int ys = tid / 48;                        // 0..3: 6-row strip
    float acc[2][6];
    #pragma unroll
    for (int o = 0; o < 2; o++)
        #pragma unroll
        for (int j = 0; j < 6; j++) acc[o][j] = 0.f;
    #pragma unroll
    for (int c = 0; c < 4; c++){
        const float* wb = w + (c>>1)*50 + (c&1)*25;
        const float* pc = p + c*1456;
        #pragma unroll
        for (int kx = 0; kx < 5; kx++){
            float v[10];
            #pragma unroll
            for (int r = 0; r < 10; r++) v[r] = pc[(ys*6 + r)*52 + x + kx];
            #pragma unroll
            for (int ky = 0; ky < 5; ky++){
                float wv = wb[ky*5 + kx];
                #pragma unroll
                for (int j = 0; j < 6; j++) acc[c>>1][j] += wv * v[j+ky];
            }
        }
    }
    float* dst = isQ ? (g_convQ + ((size_t)g*128 + op*2)*FN)
                     : (g_convK + ((size_t)bb*128 + op*2)*FN);
    #pragma unroll
    for (int o = 0; o < 2; o++){
        float bias = bsm[o];
        #pragma unroll
        for (int j = 0; j < 6; j++)
            dst[(size_t)o*FN + (half*24 + ys*6 + j)*48 + x] = acc[o][j] + bias;
    }
}

// ---------------- K: FUSED [LN+GELU+1x1+tanh] + s-transpose (64c x 128f tiles) ----------------
// grid: 9216 blocks. blk%4==0 -> ln block (2304), else sT tile (6912).
__global__ void __launch_bounds__(256) k_lnsT(
        const float* __restrict__ s1, const float* __restrict__ s2,
        const float* __restrict__ s3){
    __shared__ float sm[8448];    // ln: tile[256*33] ; sT: tile[64][129] (8256)
    __shared__ float4 spk[256];   // ln: packed {gamma,beta,w0,w1}
    int blk = blockIdx.x;
    int tid = threadIdx.x;

    if (blk % 4 != 0){
        // ---- s-transpose tile: 64 c x 128 f, fp32 -> fp16 interleaved ----
        float (*tile)[129] = (float(*)[129])sm;
        int st = blk - blk/4 - 1;             // 0..6911
        int tn = st % 3; int r = st / 3;      // r: 0..2303
        int t = r & 7; int r2 = r >> 3;       // r2: 0..287
        int ftile = r2 % 18, ctile = r2 / 18;
        int f0 = ftile*128, c0 = ctile*64;
        const float* src = (tn==0 ? s1 : tn==1 ? s2 : s3) + (size_t)t*FL*FN;
        #pragma unroll
        for (int k = 0; k < 8; k++){
            int u = tid + k*256;
            int c = u >> 5, q = u & 31;
            float4 v = *(const float4*)(src + (size_t)(c0+c)*FN + f0 + q*4);
            tile[c][q*4+0] = v.x; tile[c][q*4+1] = v.y;
            tile[c][q*4+2] = v.z; tile[c][q*4+3] = v.w;
        }
        __syncthreads();
        #pragma unroll
        for (int k = 0; k < 4; k++){
            int u = tid + k*256;
            int f = u >> 3, cp = u & 7;
            int cb = cp*8;
            __half2 h0 = __floats2half2_rn(tile[cb+0][f], tile[cb+1][f]);
            __half2 h1 = __floats2half2_rn(tile[cb+2][f], tile[cb+3][f]);
            __half2 h2 = __floats2half2_rn(tile[cb+4][f], tile[cb+5][f]);
            __half2 h3 = __floats2half2_rn(tile[cb+6][f], tile[cb+7][f]);
            uint4 u4;
            u4.x = *(unsigned*)&h0; u4.y = *(unsigned*)&h1;
            u4.z = *(unsigned*)&h2; u4.w = *(unsigned*)&h3;
            *(uint4*)(g_sT + (((size_t)t*FN + f0+f)*3 + tn)*FL + c0 + cb) = u4;
        }
        return;
    }

    // ---- ln block ----
    int ln_id = blk / 4;                      // 0..2303
    int b = ln_id / 72;                       // 0..31
    int pixbase = (ln_id % 72) * 32;
    int g = b & 3;
    float* tile = sm;                         // 256*33
    spk[tid] = g_lnpk[tid];
    for (int i = tid; i < 256*32; i += 256){
        int ch = i >> 5, pp = i & 31;
        float val;
        if (ch < 128) val = g_convQ[((size_t)g*128 + ch)*FN + pixbase + pp];
        else          val = g_convK[((size_t)b*128 + (ch-128))*FN + pixbase + pp];
        tile[ch*33 + pp] = val;
    }
    __syncthreads();
    int lane = tid & 31, wid = tid >> 5;
    for (int q = 0; q < 4; q++){
        int pp = wid*4 + q;
        float xv[8]; float s = 0.f, ss = 0.f;
        #pragma unroll
        for (int k = 0; k < 8; k++){
            float x = tile[(lane + 32*k)*33 + pp];
            xv[k] = x; s += x; ss += x*x;
        }
        for (int o = 16; o > 0; o >>= 1){
            s  += __shfl_xor_sync(~0u, s,  o);
            ss += __shfl_xor_sync(~0u, ss, o);
        }
        float mean = s * (1.0f/256.0f);
        float var  = ss * (1.0f/256.0f) - mean*mean;
        float rstd = rsqrtf(var + 1e-5f);
        float a0 = 0.f, a1 = 0.f;
        #pragma unroll
        for (int k = 0; k < 8; k++){
            float4 pk = spk[lane + 32*k];
            float y = (xv[k] - mean)*rstd*pk.x + pk.y;
            float gl = 0.5f*y*(1.0f + erf_fast(y*0.70710678118654752f));
            a0 += gl*pk.z; a1 += gl*pk.w;
        }
        for (int o = 16; o > 0; o >>= 1){
            a0 += __shfl_xor_sync(~0u, a0, o);
            a1 += __shfl_xor_sync(~0u, a1, o);
        }
        if (lane == 0){
            int pix = pixbase + pp;
            int py = pix / HS, px = pix - py*HS;
            float o0 = tanhf(a0) * (2.0f/48.0f);
            float o1 = tanhf(a1) * (2.0f/48.0f);
            float ry = (0.5f + py)*(2.0f/48.0f) - 1.0f;
            float rx = (0.5f + px)*(2.0f/48.0f) - 1.0f;
            g_gp[((size_t)b*FN + pix)*2 + 0] = (o1 + rx + 1.0f)*0.5f*47.0f;
            g_gp[((size_t)b*FN + pix)*2 + 1] = (o0 + ry + 1.0f)*0.5f*47.0f;
        }
    }
}

// ---------------- K: FUSED mat(max/argmax) + argmax-time gather/fold (uint2 gathers) ----------------
__global__ void __launch_bounds__(256) k_matsg(){
    int f = blockIdx.x, tid = threadIdx.x;
    __shared__ float4 cns4[256];
    __shared__ float part[8];
    __shared__ int   scidx;
    __shared__ __half sv[192][18];
    cns4[tid] = ((const float4*)(g_CN + (size_t)f*FL))[tid];
    __syncthreads();
    int w = tid >> 5, lane = tid & 31;
    // ---- phase 1: mat, warp-per-t ----
    {
        float acc = 0.f;
        #pragma unroll
        for (int g = 0; g < 4; g++){
            int b = w*4 + g;
            float2 sp = ((const float2*)g_gp)[(size_t)b*FN + f];
            float x0f = floorf(sp.x), y0f = floorf(sp.y);
            float wx = sp.x - x0f, wy = sp.y - y0f;
            int x0 = (int)x0f, y0 = (int)y0f;
            float4 va = make_float4(0.f,0.f,0.f,0.f);
            float4 vb = make_float4(0.f,0.f,0.f,0.f);
            #pragma unroll
            for (int dy = 0; dy < 2; dy++){
                #pragma unroll
                for (int dx = 0; dx < 2; dx++){
                    int cy = y0 + dy, cx = x0 + dx;
                    if (cy >= 0 && cy < HS && cx >= 0 && cx < HS){
                        int idx = g_gidx[w*FN + cy*HS + cx];
                        if (idx >= 0){
                            float sc = ((dy ? wy : 1.0f-wy) * (dx ? wx : 1.0f-wx))
                                       * g_inorm[w*FN + idx];
                            const float4* ip4 = (const float4*)(g_iT + ((size_t)w*FN + idx)*FL + g*256);
                            float4 u  = __ldg(&ip4[lane]);
                            float4 u2 = __ldg(&ip4[lane + 32]);
                            va.x += sc*u.x;  va.y += sc*u.y;  va.z += sc*u.z;  va.w += sc*u.w;
                            vb.x += sc*u2.x; vb.y += sc*u2.y; vb.z += sc*u2.z; vb.w += sc*u2.w;
                        }
                    }
                }
            }
            float4 ca = cns4[g*64 + lane], cb = cns4[g*64 + 32 + lane];
            acc += va.x*ca.x + va.y*ca.y + va.z*ca.z + va.w*ca.w
                 + vb.x*cb.x + vb.y*cb.y + vb.z*cb.z + vb.w*cb.w;
        }
        for (int o = 16; o > 0; o >>= 1) acc += __shfl_xor_sync(~0u, acc, o);
        if (lane == 0) part[w] = acc;
    }
    __syncthreads();
    if (tid == 0){
        float best = part[0]; int besti = 0;
        #pragma unroll
        for (int t = 1; t < 8; t++){
            if (part[t] > best){ best = part[t]; besti = t; }
        }
        g_csoft[f] = best; scidx = besti;
    }
    __syncthreads();
    // ---- phase 2: gather s1/s2/s3 at t=scidx, fold to g_fusedT ----
    int t = scidx;
    int fy = f / HS, fx = f - fy*HS;
    #pragma unroll
    for (int g = 0; g < 4; g++){
        int b = t*4 + g;
        float2 spv = ((const float2*)g_gp)[(size_t)b*FN + f];
        float x0f = floorf(spv.x), y0f = floorf(spv.y);
        float wx = spv.x - x0f, wy = spv.y - y0f;
        int x0 = (int)x0f, y0 = (int)y0f;
        size_t cbase[4]; float cwgt[4]; int nc = 0;
        #pragma unroll
        for (int dy = 0; dy < 2; dy++){
            #pragma unroll
            for (int dx = 0; dx < 2; dx++){
                int cy = y0 + dy, cx = x0 + dx;
                if (cy >= 0 && cy < HS && cx >= 0 && cx < HS){
                    int idx = g_gidx[t*FN + cy*HS + cx];
                    if (idx >= 0){
                        cbase[nc] = ((size_t)t*FN + idx)*3*FL + g*256;
                        cwgt[nc]  = (dy ? wy : 1.0f-wy) * (dx ? wx : 1.0f-wx);
                        nc++;
                    }
                }
            }
        }
        if (tid < 192){
            int tn = tid / 64;                 // 0..2
            int j  = tid - tn*64;              // 0..63
            int c4 = 4*j;                      // first half index of this uint2
            float a0 = 0.f, a1 = 0.f, a2 = 0.f, a3 = 0.f;
            for (int k = 0; k < nc; k++){
                uint2 wv = *(const uint2*)(g_sT + cbase[k] + (size_t)tn*FL + c4);
                float2 f01 = __half22float2(*(__half2*)&wv.x);
                float2 f23 = __half22float2(*(__half2*)&wv.y);
                float cw = cwgt[k];
                a0 += cw*f01.x; a1 += cw*f01.y;
                a2 += cw*f23.x; a3 += cw*f23.y;
            }
            int krow = tn*64 + g*16 + (c4 >> 4);
            int spx  = c4 & 15;
            *(__half2*)&sv[krow][spx]     = __floats2half2_rn(a0, a1);
            *(__half2*)&sv[krow][spx + 2] = __floats2half2_rn(a2, a3);
        }
    }
    __syncthreads();
    unsigned* outp = (unsigned*)g_fusedT;
    #pragma unroll
    for (int it = 0; it < 6; it++){
        int i = tid + it*256;
        int px2 = i / 96, k = i - px2*96;
        unsigned u = (unsigned)__half_as_ushort(sv[2*k][px2])
                   | ((unsigned)__half_as_ushort(sv[2*k+1][px2]) << 16);
        int gx = fx*4 + (px2 & 3), gy = fy*4 + (px2 >> 2);
        outp[((size_t)(gy*WW + gx))*96 + k] = u;
    }
}

// ---------------- K: 3x3 fusion conv via mma.sync m16n8k16 ----------------
__device__ __forceinline__ void mma16816(float& d0, float& d1, float& d2, float& d3,
                                         unsigned a0, unsigned a1, unsigned a2, unsigned a3,
                                         unsigned b0, unsigned b1){
    asm volatile(
        "mma.sync.aligned.m16n8k16.row.col.f32.f16.f16.f32 "
        "{%0,%1,%2,%3},{%4,%5,%6,%7},{%8,%9},{%0,%1,%2,%3};\n"
        : "+f"(d0), "+f"(d1), "+f"(d2), "+f"(d3)
        : "r"(a0), "r"(a1), "r"(a2), "r"(a3), "r"(b0), "r"(b1));
}

__global__ void __launch_bounds__(256, 1) k_fus(const float* __restrict__ bfus,
                                                const float* __restrict__ anchor,
                                                float* __restrict__ out){
    extern __shared__ __half xs[];            // [6 rows][66 px][pitch 200 halves]
    const unsigned* xsw = (const unsigned*)xs;
    uint4* xs4 = (uint4*)xs;
    int tid = threadIdx.x;
    int X0 = blockIdx.x*64, Y0 = blockIdx.y*4;

    for (int i = tid; i < 6*66*24; i += 256){
        int k = i % 24; int pj = i / 24; int j = pj % 66; int r = pj / 66;
        int y = Y0 - 1 + r, x = X0 - 1 + j;
        uint4 v = make_uint4(0u,0u,0u,0u);
        if (y >= 0 && y < HH && x >= 0 && x < WW)
            v = *(const uint4*)(g_fusedT + ((size_t)(y*WW + x))*192 + k*8);
        xs4[(r*66 + j)*25 + k] = v;
    }
    __syncthreads();

    int wid = tid >> 5, lane = tid & 31;
    int g = lane >> 2, tg = lane & 3;
    int ocq = wid & 3, yh = wid >> 2;
    int laneoff = g*100 + tg;

    float acc[2][8][4];
    #pragma unroll
    for (int a = 0; a < 2; a++)
        #pragma unroll
        for (int bq = 0; bq < 8; bq++)
            #pragma unroll
            for (int c = 0; c < 4; c++) acc[a][bq][c] = 0.f;

    for (int tap = 0; tap < 9; tap++){
        int ky = tap / 3, kx = tap - ky*3;
        for (int kc = 0; kc < 12; kc++){
            uint4 aa = __ldg(&g_wpk[((ocq*9 + tap)*12 + kc)*32 + lane]);
            #pragma unroll
            for (int yl = 0; yl < 2; yl++){
                int rb = ((yh*2 + yl + ky)*66 + kx)*100 + kc*8 + laneoff;
                #pragma unroll
                for (int xt = 0; xt < 8; xt++){
                    unsigned b0 = xsw[rb + xt*800];
                    unsigned b1 = xsw[rb + xt*800 + 4];
                    mma16816(acc[yl][xt][0], acc[yl][xt][1], acc[yl][xt][2], acc[yl][xt][3],
                             aa.x, aa.y, aa.z, aa.w, b0, b1);
                }
            }
        }
    }

    int oc0 = ocq*16 + g;
    float bias0 = __ldg(&bfus[oc0]);
    float bias1 = __ldg(&bfus[oc0 + 8]);
    #pragma unroll
    for (int yl = 0; yl < 2; yl++){
        int y = Y0 + yh*2 + yl;
        #pragma unroll
        for (int xt = 0; xt < 8; xt++){
            int x = X0 + xt*8 + tg*2;
            float cs = g_csoft[(y >> 2)*HS + (x >> 2)];
            size_t p0 = ((size_t)oc0*HH + y)*WW + x;
            size_t p1 = ((size_t)(oc0+8)*HH + y)*WW + x;
            float2 an0 = *(const float2*)(anchor + p0);
            float2 an1 = *(const float2*)(anchor + p1);
            float2 o0, o1;
            o0.x = (acc[yl][xt][0] + bias0)*cs + an0.x;
            o0.y = (acc[yl][xt][1] + bias0)*cs + an0.y;
            o1.x = (acc[yl][xt][2] + bias1)*cs + an1.x;
            o1.y = (acc[yl][xt][3] + bias1)*cs + an1.y;
            *(float2*)(out + p0) = o0;
            *(float2*)(out + p1) = o1;
        }
    }
}

// ---------------- launch (serial; 6 kernels) ----------------
extern "C" void kernel_launch(void* const* d_in, const int* in_sizes, int n_in,
                              void* d_out, int out_size){
    (void)in_sizes; (void)n_in; (void)out_size;
    const float* curr   = (const float*)d_in[0];
    const float* idx1   = (const float*)d_in[1];
    const float* anchor = (const float*)d_in[2];
    const float* s1     = (const float*)d_in[3];
    const float* s2     = (const float*)d_in[4];
    const float* s3     = (const float*)d_in[5];
    const float* loc    = (const float*)d_in[6];
    const float* wtdw   = (const float*)d_in[7];
    const float* btdw   = (const float*)d_in[8];
    const float* lng    = (const float*)d_in[9];
    const float* lnb    = (const float*)d_in[10];
    const float* wtpw   = (const float*)d_in[11];
    const float* wfus   = (const float*)d_in[12];
    const float* bfus   = (const float*)d_in[13];
    float* out = (float*)d_out;

    cudaFuncSetAttribute(k_fus, cudaFuncAttributeMaxDynamicSharedMemorySize, 6*66*200*2);

    // slots: [1] trIcn, [2] prep(+wpack+lnpk), [3] conv, [4] lnsT (profiled), [5] matsg, [6] fus
    k_trIcn<<<6912, 256>>>(idx1, curr);
    k_prep <<<127, 256>>>(loc, wfus, lng, lnb, wtpw);
    k_conv <<<dim3(64, 36, 2), 192>>>(wtdw, btdw);
    k_lnsT <<<9216, 256>>>(s1, s2, s3);
    k_matsg<<<FN, 256>>>();
    k_fus  <<<dim3(3, 48), 256, 6*66*200*2>>>(bfus, anchor, out);
}

// round 17
// speedup vs baseline: 1.0264x; 1.0264x over previous
#include <cuda_runtime.h>
#include <cuda_fp16.h>
#include <math.h>

#define TT 8
#define HS 48
#define FN 2304          // 48*48
#define FL 1024          // C*S*S
#define HH 192
#define WW 192
#define NB 32            // n*t*G

// ---------------- scratch ----------------
__device__ float  g_iT [(size_t)TT*FN*FL];        // idx1 transposed (fp32: argmax path)
__device__ __half g_sT [(size_t)TT*FN*3*FL];      // s1/s2/s3 interleaved [t][src][tn][c]
__device__ float  g_CN [(size_t)FN*FL];
__device__ float  g_convQ[(size_t)4*128*FN];      // Q-half conv out (per g, shared over t)
__device__ float  g_convK[(size_t)NB*128*FN];     // K-half conv out (per b)
__device__ float  g_gp [(size_t)NB*FN*2];
__device__ float  g_csoft[FN];
__device__ int    g_gidx [TT*FN];
__device__ float  g_inorm[TT*FN];
__device__ float2 g_gpk [TT*FN];                  // packed (idx as float-bits, inorm[idx])
__device__ float  g_sspart[(size_t)16*TT*FN];
__device__ __half g_fusedT[(size_t)HH*WW*192];    // pixel-major fused features
__device__ uint4  g_wpk[4*9*12*32];               // fusion weights as mma A-fragments
__device__ float4 g_lnpk[256];                    // packed {gamma, beta, w0, w1} per channel

// Abramowitz–Stegun 7.1.26 erf, |abs err| <= ~1.5e-7
__device__ __forceinline__ float erf_fast(float x){
    float ax = fabsf(x);
    float t = __fdividef(1.0f, fmaf(0.3275911f, ax, 1.0f));
    float p = fmaf(t, 1.061405429f, -1.453152027f);
    p = fmaf(t, p, 1.421413741f);
    p = fmaf(t, p, -0.284496736f);
    p = fmaf(t, p, 0.254829592f);
    p = p * t;
    float e = __expf(-ax*ax);
    float r = fmaf(-p, e, 1.0f);
    return copysignf(r, x);
}

__device__ __forceinline__ unsigned pkh(float a, float b){
    return (unsigned)__half_as_ushort(__float2half(a))
         | ((unsigned)__half_as_ushort(__float2half(b)) << 16);
}

// ---------------- K: MERGED [idx1 transpose + norm partials] + [cn unfold/normalize] ----------------
__global__ void __launch_bounds__(256) k_trIcn(const float* __restrict__ idx1,
                                               const float* __restrict__ curr){
    __shared__ float tile[64][65];
    int bid = blockIdx.x;
    int tid = threadIdx.x;

    if (bid < 4608){
        int t = bid / 576;
        int rem = bid - t*576;
        int f0 = (rem % 36)*64, c0 = (rem / 36)*64;
        const float* src = idx1 + (size_t)t*FL*FN;
        #pragma unroll
        for (int k = 0; k < 4; k++){
            int u = tid + k*256;
            int c = u >> 4, q = u & 15;
            float4 v = *(const float4*)(src + (size_t)(c0+c)*FN + f0 + q*4);
            tile[c][q*4+0] = v.x; tile[c][q*4+1] = v.y;
            tile[c][q*4+2] = v.z; tile[c][q*4+3] = v.w;
        }
        __syncthreads();
        #pragma unroll
        for (int k = 0; k < 4; k++){
            int u = tid + k*256;
            int f = u >> 4, q = u & 15;
            float4 v = make_float4(tile[q*4+0][f], tile[q*4+1][f],
                                   tile[q*4+2][f], tile[q*4+3][f]);
            *(float4*)(g_iT + ((size_t)t*FN + f0+f)*FL + c0 + q*4) = v;
            float s = v.x*v.x + v.y*v.y + v.z*v.z + v.w*v.w;
            s += __shfl_xor_sync(~0u, s, 1);
            s += __shfl_xor_sync(~0u, s, 2);
            s += __shfl_xor_sync(~0u, s, 4);
            s += __shfl_xor_sync(~0u, s, 8);
            if (q == 0)
                g_sspart[(size_t)(rem/36)*(TT*FN) + t*FN + f0+f] = s;
        }
        return;
    }

    // ---- cn block ----
    int f = bid - 4608;
    int fy = f / HS, fx = f - fy*HS;
    float v[4]; float ss = 0.f;
    #pragma unroll
    for (int k = 0; k < 4; k++){
        int cf = k*256 + tid;
        int c = cf >> 4, rem = cf & 15, sy = rem >> 2, sx = rem & 3;
        float x = curr[((size_t)c*HH + (fy*4+sy))*WW + (fx*4+sx)];
        v[k] = x; ss += x*x;
    }
    for (int o = 16; o > 0; o >>= 1) ss += __shfl_xor_sync(~0u, ss, o);
    float* ws = &tile[0][0];
    float* invs = &tile[0][8];
    if ((tid & 31) == 0) ws[tid>>5] = ss;
    __syncthreads();
    if (tid == 0){
        float s = 0.f;
        #pragma unroll
        for (int k = 0; k < 8; k++) s += ws[k];
        *invs = 1.0f / fmaxf(sqrtf(s), 1e-12f);
    }
    __syncthreads();
    float iv = *invs;
    #pragma unroll
    for (int k = 0; k < 4; k++) g_CN[(size_t)f*FL + k*256 + tid] = v[k]*iv;
}

// ---------------- K: gidx + inorm finalize + wpack + ln-param pack ----------------
// grid: 127 blocks. bid<72: prep; bid in [72,126): wpack; bid==126: lnpk.
__global__ void k_prep(const float* __restrict__ loc, const float* __restrict__ wfus,
                       const float* __restrict__ lng, const float* __restrict__ lnb,
                       const float* __restrict__ wtpw){
    int bid = blockIdx.x;
    int tid = threadIdx.x;
    if (bid < 72){
        int i = bid*256 + tid;
        int t = i / FN, f = i - t*FN;
        float lx = loc[(t*2+0)*FN + f];
        float ly = loc[(t*2+1)*FN + f];
        int ix = __float2int_rn(lx);
        int iy = __float2int_rn(ly);
        bool valid = (ix>=0 && ix<HS && iy>=0 && iy<HS);
        g_gidx[i] = valid ? (iy*HS + ix) : -1;
        float s = 0.f;
        #pragma unroll
        for (int k = 0; k < 16; k++) s += g_sspart[(size_t)k*(TT*FN) + i];
        g_inorm[i] = 1.0f / fmaxf(sqrtf(s), 1e-12f);
        return;
    }
    if (bid < 126){
        int idx = (bid - 72)*256 + tid;       // < 13824 = 4*9*12*32
        int lane = idx & 31;
        int rest = idx >> 5;
        int kc = rest % 12; rest /= 12;
        int tap = rest % 9;
        int ocq = rest / 9;
        int g = lane >> 2, tg = lane & 3;
        int r0 = ocq*16 + g, r1 = r0 + 8;
        int k0 = kc*16 + tg*2;
        #define WF(r,k) wfus[((size_t)(r)*192 + (k))*9 + tap]
        uint4 u;
        u.x = pkh(WF(r0, k0),   WF(r0, k0+1));
        u.y = pkh(WF(r1, k0),   WF(r1, k0+1));
        u.z = pkh(WF(r0, k0+8), WF(r0, k0+9));
        u.w = pkh(WF(r1, k0+8), WF(r1, k0+9));
        #undef WF
        g_wpk[idx] = u;
        return;
    }
    // bid == 126: pack ln params
    g_lnpk[tid] = make_float4(lng[tid], lnb[tid], wtpw[tid], wtpw[256 + tid]);
}

// ---------------- K: pack (gidx, inorm[gidx]) pairs ----------------
__global__ void k_pack(){
    int i = blockIdx.x*256 + threadIdx.x;     // < TT*FN (72 blocks)
    int t = i / FN;
    int idx = g_gidx[i];
    float inr = (idx >= 0) ? g_inorm[t*FN + idx] : 0.f;
    g_gpk[i] = make_float2(__int_as_float(idx), inr);
}

// ---------------- K: grouped 5x5 conv, 2 out-ch/block, batched-MLP fill ----------------
__global__ void __launch_bounds__(192, 8) k_conv(const float* __restrict__ wtdw,
                                                 const float* __restrict__ btdw){
    __shared__ float p[4*1456];               // 4 planes x 28 rows x 52
    __shared__ float w[100];
    __shared__ float bsm[2];
    int op = blockIdx.x;
    int yb = blockIdx.y;
    int half = blockIdx.z;
    bool isQ = (yb < 4);
    int g, t = 0, bb = 0;
    if (isQ){ g = yb; } else { bb = yb - 4; t = bb >> 2; g = bb & 3; }
    int o0 = (isQ ? 0 : 128) + op*2;
    int ch0 = g*256 + op*4;
    int tid = threadIdx.x;
    for (int i = tid; i < 100; i += 192) w[i] = wtdw[(size_t)o0*50 + i];
    if (tid < 2) bsm[tid] = btdw[o0 + tid];
    int ybase = half*24 - 2;
    // ---- fill: 2 outer x 4-wide batched gathers (MLP 4) ----
    #pragma unroll
    for (int base = 0; base < 2; base++){
        int idxv[4]; float inrv[4]; int pixv[4];
        #pragma unroll
        for (int k = 0; k < 4; k++){
            int pix = base*768 + k*192 + tid;
            pixv[k] = pix;
            idxv[k] = -1; inrv[k] = 1.f;
            if (pix < 1456){
                int yy = pix/52 + ybase, xx = pix%52 - 2;
                if (yy >= 0 && yy < HS && xx >= 0 && xx < HS){
                    int f = yy*HS + xx;
                    if (isQ){
                        idxv[k] = f;
                    } else {
                        float2 pk = g_gpk[t*FN + f];
                        idxv[k] = __float_as_int(pk.x);
                        inrv[k] = pk.y;
                    }
                }
            }
        }
        float4 v4[4];
        #pragma unroll
        for (int k = 0; k < 4; k++){
            float4 v = make_float4(0.f,0.f,0.f,0.f);
            if (idxv[k] >= 0){
                const float* bp = isQ ? (g_CN + (size_t)idxv[k]*FL + ch0)
                                      : (g_iT + ((size_t)t*FN + idxv[k])*FL + ch0);
                v = *(const float4*)bp;
                v.x *= inrv[k]; v.y *= inrv[k]; v.z *= inrv[k]; v.w *= inrv[k];
            }
            v4[k] = v;
        }
        #pragma unroll
        for (int k = 0; k < 4; k++){
            if (pixv[k] < 1456){
                p[0*1456 + pixv[k]] = v4[k].x;
                p[1*1456 + pixv[k]] = v4[k].y;
                p[2*1456 + pixv[k]] = v4[k].z;
                p[3*1456 + pixv[k]] = v4[k].w;
            }
        }
    }
    __syncthreads();
    int x  = tid % 48;
    int ys = tid / 48;                        // 0..3: 6-row strip
    float acc[2][6];
    #pragma unroll
    for (int o = 0; o < 2; o++)
        #pragma unroll
        for (int j = 0; j < 6; j++) acc[o][j] = 0.f;
    #pragma unroll
    for (int c = 0; c < 4; c++){
        const float* wb = w + (c>>1)*50 + (c&1)*25;
        const float* pc = p + c*1456;
        #pragma unroll
        for (int kx = 0; kx < 5; kx++){
            float v[10];
            #pragma unroll
            for (int r = 0; r < 10; r++) v[r] = pc[(ys*6 + r)*52 + x + kx];
            #pragma unroll
            for (int ky = 0; ky < 5; ky++){
                float wv = wb[ky*5 + kx];
                #pragma unroll
                for (int j = 0; j < 6; j++) acc[c>>1][j] += wv * v[j+ky];
            }
        }
    }
    float* dst = isQ ? (g_convQ + ((size_t)g*128 + op*2)*FN)
                     : (g_convK + ((size_t)bb*128 + op*2)*FN);
    #pragma unroll
    for (int o = 0; o < 2; o++){
        float bias = bsm[o];
        #pragma unroll
        for (int j = 0; j < 6; j++)
            dst[(size_t)o*FN + (half*24 + ys*6 + j)*48 + x] = acc[o][j] + bias;
    }
}

// ---------------- K: FUSED [LN+GELU+1x1+tanh] + s-transpose (64c x 128f tiles) ----------------
// grid: 9216 blocks. blk%4==0 -> ln block (2304), else sT tile (6912).
__global__ void __launch_bounds__(256) k_lnsT(
        const float* __restrict__ s1, const float* __restrict__ s2,
        const float* __restrict__ s3){
    __shared__ float sm[8448];    // ln: tile[256*33] ; sT: tile[64][129] (8256)
    __shared__ float4 spk[256];   // ln: packed {gamma,beta,w0,w1}
    int blk = blockIdx.x;
    int tid = threadIdx.x;

    if (blk % 4 != 0){
        // ---- s-transpose tile: 64 c x 128 f, fp32 -> fp16 interleaved ----
        float (*tile)[129] = (float(*)[129])sm;
        int st = blk - blk/4 - 1;             // 0..6911
        int tn = st % 3; int r = st / 3;      // r: 0..2303
        int t = r & 7; int r2 = r >> 3;       // r2: 0..287
        int ftile = r2 % 18, ctile = r2 / 18;
        int f0 = ftile*128, c0 = ctile*64;
        const float* src = (tn==0 ? s1 : tn==1 ? s2 : s3) + (size_t)t*FL*FN;
        #pragma unroll
        for (int k = 0; k < 8; k++){
            int u = tid + k*256;
            int c = u >> 5, q = u & 31;
            float4 v = *(const float4*)(src + (size_t)(c0+c)*FN + f0 + q*4);
            tile[c][q*4+0] = v.x; tile[c][q*4+1] = v.y;
            tile[c][q*4+2] = v.z; tile[c][q*4+3] = v.w;
        }
        __syncthreads();
        #pragma unroll
        for (int k = 0; k < 4; k++){
            int u = tid + k*256;
            int f = u >> 3, cp = u & 7;
            int cb = cp*8;
            __half2 h0 = __floats2half2_rn(tile[cb+0][f], tile[cb+1][f]);
            __half2 h1 = __floats2half2_rn(tile[cb+2][f], tile[cb+3][f]);
            __half2 h2 = __floats2half2_rn(tile[cb+4][f], tile[cb+5][f]);
            __half2 h3 = __floats2half2_rn(tile[cb+6][f], tile[cb+7][f]);
            uint4 u4;
            u4.x = *(unsigned*)&h0; u4.y = *(unsigned*)&h1;
            u4.z = *(unsigned*)&h2; u4.w = *(unsigned*)&h3;
            *(uint4*)(g_sT + (((size_t)t*FN + f0+f)*3 + tn)*FL + c0 + cb) = u4;
        }
        return;
    }

    // ---- ln block ----
    int ln_id = blk / 4;                      // 0..2303
    int b = ln_id / 72;                       // 0..31
    int pixbase = (ln_id % 72) * 32;
    int g = b & 3;
    float* tile = sm;                         // 256*33
    spk[tid] = g_lnpk[tid];
    for (int i = tid; i < 256*32; i += 256){
        int ch = i >> 5, pp = i & 31;
        float val;
        if (ch < 128) val = g_convQ[((size_t)g*128 + ch)*FN + pixbase + pp];
        else          val = g_convK[((size_t)b*128 + (ch-128))*FN + pixbase + pp];
        tile[ch*33 + pp] = val;
    }
    __syncthreads();
    int lane = tid & 31, wid = tid >> 5;
    for (int q = 0; q < 4; q++){
        int pp = wid*4 + q;
        float xv[8]; float s = 0.f, ss = 0.f;
        #pragma unroll
        for (int k = 0; k < 8; k++){
            float x = tile[(lane + 32*k)*33 + pp];
            xv[k] = x; s += x; ss += x*x;
        }
        for (int o = 16; o > 0; o >>= 1){
            s  += __shfl_xor_sync(~0u, s,  o);
            ss += __shfl_xor_sync(~0u, ss, o);
        }
        float mean = s * (1.0f/256.0f);
        float var  = ss * (1.0f/256.0f) - mean*mean;
        float rstd = rsqrtf(var + 1e-5f);
        float a0 = 0.f, a1 = 0.f;
        #pragma unroll
        for (int k = 0; k < 8; k++){
            float4 pk = spk[lane + 32*k];
            float y = (xv[k] - mean)*rstd*pk.x + pk.y;
            float gl = 0.5f*y*(1.0f + erf_fast(y*0.70710678118654752f));
            a0 += gl*pk.z; a1 += gl*pk.w;
        }
        for (int o = 16; o > 0; o >>= 1){
            a0 += __shfl_xor_sync(~0u, a0, o);
            a1 += __shfl_xor_sync(~0u, a1, o);
        }
        if (lane == 0){
            int pix = pixbase + pp;
            int py = pix / HS, px = pix - py*HS;
            float o0 = tanhf(a0) * (2.0f/48.0f);
            float o1 = tanhf(a1) * (2.0f/48.0f);
            float ry = (0.5f + py)*(2.0f/48.0f) - 1.0f;
            float rx = (0.5f + px)*(2.0f/48.0f) - 1.0f;
            g_gp[((size_t)b*FN + pix)*2 + 0] = (o1 + rx + 1.0f)*0.5f*47.0f;
            g_gp[((size_t)b*FN + pix)*2 + 1] = (o0 + ry + 1.0f)*0.5f*47.0f;
        }
    }
}

// ---------------- K: FUSED mat(max/argmax) + argmax-time gather/fold ----------------
__global__ void __launch_bounds__(256) k_matsg(){
    int f = blockIdx.x, tid = threadIdx.x;
    __shared__ float4 cns4[256];
    __shared__ float part[8];
    __shared__ int   scidx;
    __shared__ __half sv[192][18];
    cns4[tid] = ((const float4*)(g_CN + (size_t)f*FL))[tid];
    __syncthreads();
    int w = tid >> 5, lane = tid & 31;
    // ---- phase 1: mat, warp-per-t (packed idx+inorm) ----
    {
        float acc = 0.f;
        #pragma unroll
        for (int g = 0; g < 4; g++){
            int b = w*4 + g;
            float2 sp = ((const float2*)g_gp)[(size_t)b*FN + f];
            float x0f = floorf(sp.x), y0f = floorf(sp.y);
            float wx = sp.x - x0f, wy = sp.y - y0f;
            int x0 = (int)x0f, y0 = (int)y0f;
            float4 va = make_float4(0.f,0.f,0.f,0.f);
            float4 vb = make_float4(0.f,0.f,0.f,0.f);
            #pragma unroll
            for (int dy = 0; dy < 2; dy++){
                #pragma unroll
                for (int dx = 0; dx < 2; dx++){
                    int cy = y0 + dy, cx = x0 + dx;
                    if (cy >= 0 && cy < HS && cx >= 0 && cx < HS){
                        float2 pk = g_gpk[w*FN + cy*HS + cx];
                        int idx = __float_as_int(pk.x);
                        if (idx >= 0){
                            float sc = ((dy ? wy : 1.0f-wy) * (dx ? wx : 1.0f-wx)) * pk.y;
                            const float4* ip4 = (const float4*)(g_iT + ((size_t)w*FN + idx)*FL + g*256);
                            float4 u  = __ldg(&ip4[lane]);
                            float4 u2 = __ldg(&ip4[lane + 32]);
                            va.x += sc*u.x;  va.y += sc*u.y;  va.z += sc*u.z;  va.w += sc*u.w;
                            vb.x += sc*u2.x; vb.y += sc*u2.y; vb.z += sc*u2.z; vb.w += sc*u2.w;
                        }
                    }
                }
            }
            float4 ca = cns4[g*64 + lane], cb = cns4[g*64 + 32 + lane];
            acc += va.x*ca.x + va.y*ca.y + va.z*ca.z + va.w*ca.w
                 + vb.x*cb.x + vb.y*cb.y + vb.z*cb.z + vb.w*cb.w;
        }
        for (int o = 16; o > 0; o >>= 1) acc += __shfl_xor_sync(~0u, acc, o);
        if (lane == 0) part[w] = acc;
    }
    __syncthreads();
    if (tid == 0){
        float best = part[0]; int besti = 0;
        #pragma unroll
        for (int t = 1; t < 8; t++){
            if (part[t] > best){ best = part[t]; besti = t; }
        }
        g_csoft[f] = best; scidx = besti;
    }
    __syncthreads();
    // ---- phase 2: gather s1/s2/s3 at t=scidx, fold to g_fusedT ----
    int t = scidx;
    int fy = f / HS, fx = f - fy*HS;
    #pragma unroll
    for (int g = 0; g < 4; g++){
        int b = t*4 + g;
        float2 spv = ((const float2*)g_gp)[(size_t)b*FN + f];
        float x0f = floorf(spv.x), y0f = floorf(spv.y);
        float wx = spv.x - x0f, wy = spv.y - y0f;
        int x0 = (int)x0f, y0 = (int)y0f;
        size_t cbase[4]; float cwgt[4]; int nc = 0;
        #pragma unroll
        for (int dy = 0; dy < 2; dy++){
            #pragma unroll
            for (int dx = 0; dx < 2; dx++){
                int cy = y0 + dy, cx = x0 + dx;
                if (cy >= 0 && cy < HS && cx >= 0 && cx < HS){
                    float2 pk = g_gpk[t*FN + cy*HS + cx];
                    int idx = __float_as_int(pk.x);
                    if (idx >= 0){
                        cbase[nc] = ((size_t)t*FN + idx)*3*FL + g*256;
                        cwgt[nc]  = (dy ? wy : 1.0f-wy) * (dx ? wx : 1.0f-wx);
                        nc++;
                    }
                }
            }
        }
        if (tid < 192){
            int tn = tid / 64;                 // 0..2
            int j  = tid - tn*64;              // 0..63
            int c4 = 4*j;                      // first half index of this uint2
            float a0 = 0.f, a1 = 0.f, a2 = 0.f, a3 = 0.f;
            for (int k = 0; k < nc; k++){
                uint2 wv = *(const uint2*)(g_sT + cbase[k] + (size_t)tn*FL + c4);
                float2 f01 = __half22float2(*(__half2*)&wv.x);
                float2 f23 = __half22float2(*(__half2*)&wv.y);
                float cw = cwgt[k];
                a0 += cw*f01.x; a1 += cw*f01.y;
                a2 += cw*f23.x; a3 += cw*f23.y;
            }
            int krow = tn*64 + g*16 + (c4 >> 4);
            int spx  = c4 & 15;
            *(__half2*)&sv[krow][spx]     = __floats2half2_rn(a0, a1);
            *(__half2*)&sv[krow][spx + 2] = __floats2half2_rn(a2, a3);
        }
    }
    __syncthreads();
    unsigned* outp = (unsigned*)g_fusedT;
    #pragma unroll
    for (int it = 0; it < 6; it++){
        int i = tid + it*256;
        int px2 = i / 96, k = i - px2*96;
        unsigned u = (unsigned)__half_as_ushort(sv[2*k][px2])
                   | ((unsigned)__half_as_ushort(sv[2*k+1][px2]) << 16);
        int gx = fx*4 + (px2 & 3), gy = fy*4 + (px2 >> 2);
        outp[((size_t)(gy*WW + gx))*96 + k] = u;
    }
}

// ---------------- K: 3x3 fusion conv via mma.sync m16n8k16 ----------------
__device__ __forceinline__ void mma16816(float& d0, float& d1, float& d2, float& d3,
                                         unsigned a0, unsigned a1, unsigned a2, unsigned a3,
                                         unsigned b0, unsigned b1){
    asm volatile(
        "mma.sync.aligned.m16n8k16.row.col.f32.f16.f16.f32 "
        "{%0,%1,%2,%3},{%4,%5,%6,%7},{%8,%9},{%0,%1,%2,%3};\n"
        : "+f"(d0), "+f"(d1), "+f"(d2), "+f"(d3)
        : "r"(a0), "r"(a1), "r"(a2), "r"(a3), "r"(b0), "r"(b1));
}

__global__ void __launch_bounds__(256, 1) k_fus(const float* __restrict__ bfus,
                                                const float* __restrict__ anchor,
                                                float* __restrict__ out){
    extern __shared__ __half xs[];            // [6 rows][66 px][pitch 200 halves]
    const unsigned* xsw = (const unsigned*)xs;
    uint4* xs4 = (uint4*)xs;
    int tid = threadIdx.x;
    int X0 = blockIdx.x*64, Y0 = blockIdx.y*4;

    for (int i = tid; i < 6*66*24; i += 256){
        int k = i % 24; int pj = i / 24; int j = pj % 66; int r = pj / 66;
        int y = Y0 - 1 + r, x = X0 - 1 + j;
        uint4 v = make_uint4(0u,0u,0u,0u);
        if (y >= 0 && y < HH && x >= 0 && x < WW)
            v = *(const uint4*)(g_fusedT + ((size_t)(y*WW + x))*192 + k*8);
        xs4[(r*66 + j)*25 + k] = v;
    }
    __syncthreads();

    int wid = tid >> 5, lane = tid & 31;
    int g = lane >> 2, tg = lane & 3;
    int ocq = wid & 3, yh = wid >> 2;
    int laneoff = g*100 + tg;

    float acc[2][8][4];
    #pragma unroll
    for (int a = 0; a < 2; a++)
        #pragma unroll
        for (int bq = 0; bq < 8; bq++)
            #pragma unroll
            for (int c = 0; c < 4; c++) acc[a][bq][c] = 0.f;

    for (int tap = 0; tap < 9; tap++){
        int ky = tap / 3, kx = tap - ky*3;
        for (int kc = 0; kc < 12; kc++){
            uint4 aa = __ldg(&g_wpk[((ocq*9 + tap)*12 + kc)*32 + lane]);
            #pragma unroll
            for (int yl = 0; yl < 2; yl++){
                int rb = ((yh*2 + yl + ky)*66 + kx)*100 + kc*8 + laneoff;
                #pragma unroll
                for (int xt = 0; xt < 8; xt++){
                    unsigned b0 = xsw[rb + xt*800];
                    unsigned b1 = xsw[rb + xt*800 + 4];
                    mma16816(acc[yl][xt][0], acc[yl][xt][1], acc[yl][xt][2], acc[yl][xt][3],
                             aa.x, aa.y, aa.z, aa.w, b0, b1);
                }
            }
        }
    }

    int oc0 = ocq*16 + g;
    float bias0 = __ldg(&bfus[oc0]);
    float bias1 = __ldg(&bfus[oc0 + 8]);
    #pragma unroll
    for (int yl = 0; yl < 2; yl++){
        int y = Y0 + yh*2 + yl;
        #pragma unroll
        for (int xt = 0; xt < 8; xt++){
            int x = X0 + xt*8 + tg*2;
            float cs = g_csoft[(y >> 2)*HS + (x >> 2)];
            size_t p0 = ((size_t)oc0*HH + y)*WW + x;
            size_t p1 = ((size_t)(oc0+8)*HH + y)*WW + x;
            float2 an0 = *(const float2*)(anchor + p0);
            float2 an1 = *(const float2*)(anchor + p1);
            float2 o0, o1;
            o0.x = (acc[yl][xt][0] + bias0)*cs + an0.x;
            o0.y = (acc[yl][xt][1] + bias0)*cs + an0.y;
            o1.x = (acc[yl][xt][2] + bias1)*cs + an1.x;
            o1.y = (acc[yl][xt][3] + bias1)*cs + an1.y;
            *(float2*)(out + p0) = o0;
            *(float2*)(out + p1) = o1;
        }
    }
}

// ---------------- launch (serial; 7 kernels) ----------------
extern "C" void kernel_launch(void* const* d_in, const int* in_sizes, int n_in,
                              void* d_out, int out_size){
    (void)in_sizes; (void)n_in; (void)out_size;
    const float* curr   = (const float*)d_in[0];
    const float* idx1   = (const float*)d_in[1];
    const float* anchor = (const float*)d_in[2];
    const float* s1     = (const float*)d_in[3];
    const float* s2     = (const float*)d_in[4];
    const float* s3     = (const float*)d_in[5];
    const float* loc    = (const float*)d_in[6];
    const float* wtdw   = (const float*)d_in[7];
    const float* btdw   = (const float*)d_in[8];
    const float* lng    = (const float*)d_in[9];
    const float* lnb    = (const float*)d_in[10];
    const float* wtpw   = (const float*)d_in[11];
    const float* wfus   = (const float*)d_in[12];
    const float* bfus   = (const float*)d_in[13];
    float* out = (float*)d_out;

    cudaFuncSetAttribute(k_fus, cudaFuncAttributeMaxDynamicSharedMemorySize, 6*66*200*2);

    // slots: [1] trIcn, [2] prep, [3] pack, [4] conv (profiled), [5] lnsT, [6] matsg, [7] fus
    k_trIcn<<<6912, 256>>>(idx1, curr);
    k_prep <<<127, 256>>>(loc, wfus, lng, lnb, wtpw);
    k_pack <<<72, 256>>>();
    k_conv <<<dim3(64, 36, 2), 192>>>(wtdw, btdw);
    k_lnsT <<<9216, 256>>>(s1, s2, s3);
    k_matsg<<<FN, 256>>>();
    k_fus  <<<dim3(3, 48), 256, 6*66*200*2>>>(bfus, anchor, out);
}